// round 2
// baseline (speedup 1.0000x reference)
#include <cuda_runtime.h>
#include <cuda_bf16.h>

#define BATCH      131072
#define HID        256
#define SPIKE_DIM  128
#define COORD_DIM  64
#define IN_DIM     192
#define NUM_STEPS  25
#define BETA       0.7f
#define OMB        (1.0f - BETA)

#define TILES      (BATCH / 128)   // 1024
#define XP         100             // bf16x2 words per X row (96 used + pad, ==4 mod 32)
#define WP         100             // bf16x2 words per W row
#define TH         0.80f           // classifier threshold (0.999 - bf16 error margin)

// ---------------- device scratch ----------------
__device__ unsigned g_W0b2[HID * WP];          // W0 packed bf16x2, [j][k2]
__device__ int      g_flags[BATCH];
__device__ float    g_W1T[HID * HID];          // W1T[j][i] = W1[i][j]
__device__ float    g_WcT[HID * COORD_DIM];    // WcT[i][m] = W_out[128+m][i]
__device__ unsigned g_wmax_u, g_bmax_u;
__device__ int      g_Hlim;
__device__ unsigned g_tile;

// ---------------- helpers ----------------
__device__ __forceinline__ unsigned pk(float lo, float hi) {
    __nv_bfloat162 h;
    h.x = __float2bfloat16_rn(lo);   // low half  = first (even-k) element
    h.y = __float2bfloat16_rn(hi);   // high half = second (odd-k) element
    return *reinterpret_cast<unsigned*>(&h);
}

__device__ __forceinline__ void mma16816(float c[4], const unsigned a[4], const unsigned b[2]) {
    asm volatile(
        "mma.sync.aligned.m16n8k16.row.col.f32.bf16.bf16.f32 "
        "{%0,%1,%2,%3}, {%4,%5,%6,%7}, {%8,%9}, {%0,%1,%2,%3};"
        : "+f"(c[0]), "+f"(c[1]), "+f"(c[2]), "+f"(c[3])
        : "r"(a[0]), "r"(a[1]), "r"(a[2]), "r"(a[3]), "r"(b[0]), "r"(b[1]));
}

// ---------------- prep ----------------
__global__ void k_init() { g_wmax_u = 0u; g_bmax_u = 0u; g_tile = 0u; }

__global__ void k_prep(const float* __restrict__ W1, const float* __restrict__ b1,
                       const float* __restrict__ W_out) {
    int i = blockIdx.x;    // 0..255
    int j = threadIdx.x;   // 0..255
    float v = W1[i * HID + j];
    g_W1T[j * HID + i] = v;

    float m = fabsf(v);
    #pragma unroll
    for (int off = 16; off; off >>= 1) m = fmaxf(m, __shfl_xor_sync(~0u, m, off));
    __shared__ float sm[8];
    int w = j >> 5, l = j & 31;
    if (l == 0) sm[w] = m;
    __syncthreads();
    if (j < 8) {
        float t = sm[j];
        #pragma unroll
        for (int off = 4; off; off >>= 1) t = fmaxf(t, __shfl_xor_sync(0xffu, t, off));
        if (j == 0) atomicMax(&g_wmax_u, __float_as_uint(t));
    }
    if (i == 0) atomicMax(&g_bmax_u, __float_as_uint(fabsf(b1[j])));

    if (i < COORD_DIM)
        g_WcT[j * COORD_DIM + i] = W_out[(SPIKE_DIM + i) * HID + j];
}

__global__ void k_prepW0(const float* __restrict__ W0) {
    int j  = blockIdx.x;     // 0..255
    int k2 = threadIdx.x;    // 0..95
    g_W0b2[j * WP + k2] = pk(W0[j * IN_DIM + 2 * k2], W0[j * IN_DIM + 2 * k2 + 1]);
}

__global__ void k_finalize() {
    float wmax = __uint_as_float(g_wmax_u);
    float bmax = __uint_as_float(g_bmax_u);
    int hl;
    if (bmax >= 0.995f)      hl = -1;
    else if (wmax <= 0.0f)   hl = 1 << 30;
    else                     hl = (int)floorf((0.995f - bmax) / wmax);
    g_Hlim = hl;
}

// ---------------- bf16 tensor-core GEMM + classifier ----------------
// block tile 128(M) x 256(N), K=192. 8 warps = 2(M) x 4(N), warp tile 64x64.
#define GEMM_SMEM ((HID * WP + 128 * XP) * 4 + 256 * 4 + 128 * 4)

__global__ __launch_bounds__(256, 1)
void k_gemm(const float* __restrict__ spikes, const float* __restrict__ coords,
            const float* __restrict__ b0) {
    extern __shared__ unsigned sh[];
    unsigned* Ws  = sh;                        // [256][WP]
    unsigned* Xs  = sh + HID * WP;             // [128][XP]
    float*    b0s = (float*)(Xs + 128 * XP);   // [256]
    int*      cnt = (int*)(b0s + 256);         // [128]
    __shared__ unsigned s_tile;

    int tid  = threadIdx.x;
    int lane = tid & 31;
    int wid  = tid >> 5;
    int g  = lane >> 2, qp = lane & 3;
    int wm = wid >> 2,  wn = wid & 3;

    // one-time: W0 bf16x2 into smem (coalesced float4 copy), b0 into smem
    {
        const float4* wsrc = (const float4*)g_W0b2;
        float4* wdst = (float4*)Ws;
        #pragma unroll
        for (int i = 0; i < 25; i++) wdst[i * 256 + tid] = wsrc[i * 256 + tid];
        b0s[tid] = b0[tid];
    }
    int Hlim = g_Hlim;

    for (;;) {
        __syncthreads();                       // protects Xs/cnt reuse
        if (tid == 0) s_tile = atomicAdd(&g_tile, 1u);
        if (tid < 128) cnt[tid] = 0;
        __syncthreads();
        unsigned tile = s_tile;
        if (tile >= TILES) break;
        int R0 = (int)tile * 128;

        // load + convert X tile -> Xs [row][k2] bf16x2
        #pragma unroll
        for (int it = 0; it < 24; it++) {
            int idx = it * 256 + tid;
            int row = idx / 48, f4 = idx % 48;
            float4 v;
            if (f4 < 32) v = ((const float4*)(spikes + (size_t)(R0 + row) * SPIKE_DIM))[f4];
            else         v = ((const float4*)(coords + (size_t)(R0 + row) * COORD_DIM))[f4 - 32];
            unsigned w0 = pk(v.x, v.y), w1 = pk(v.z, v.w);
            *(uint2*)(Xs + row * XP + 2 * f4) = make_uint2(w0, w1);
        }
        __syncthreads();

        #pragma unroll 1
        for (int h = 0; h < 2; h++) {          // n-halves to cap register use
            float cf[4][4][4];
            #pragma unroll
            for (int mt = 0; mt < 4; mt++)
                #pragma unroll
                for (int nt = 0; nt < 4; nt++)
                    #pragma unroll
                    for (int q = 0; q < 4; q++) cf[mt][nt][q] = 0.0f;

            #pragma unroll
            for (int kk = 0; kk < 12; kk++) {
                int k2b = kk * 8;
                unsigned a[4][4];
                #pragma unroll
                for (int mt = 0; mt < 4; mt++) {
                    const unsigned* xr = Xs + (wm * 64 + mt * 16 + g) * XP + k2b + qp;
                    a[mt][0] = xr[0];
                    a[mt][1] = xr[8 * XP];
                    a[mt][2] = xr[4];
                    a[mt][3] = xr[8 * XP + 4];
                }
                unsigned bf[4][2];
                #pragma unroll
                for (int nt = 0; nt < 4; nt++) {
                    const unsigned* wr = Ws + (wn * 64 + h * 32 + nt * 8 + g) * WP + k2b + qp;
                    bf[nt][0] = wr[0];
                    bf[nt][1] = wr[4];
                }
                #pragma unroll
                for (int mt = 0; mt < 4; mt++)
                    #pragma unroll
                    for (int nt = 0; nt < 4; nt++)
                        mma16816(cf[mt][nt], a[mt], bf[nt]);
            }

            // epilogue: +b0, hot-count per row
            #pragma unroll
            for (int mt = 0; mt < 4; mt++) {
                int r0 = wm * 64 + mt * 16 + g;
                int c0n = 0, c1n = 0;
                #pragma unroll
                for (int nt = 0; nt < 4; nt++) {
                    int c = wn * 64 + h * 32 + nt * 8 + 2 * qp;
                    float bA = b0s[c], bB = b0s[c + 1];
                    c0n += (cf[mt][nt][0] + bA >= TH) ? 1 : 0;
                    c0n += (cf[mt][nt][1] + bB >= TH) ? 1 : 0;
                    c1n += (cf[mt][nt][2] + bA >= TH) ? 1 : 0;
                    c1n += (cf[mt][nt][3] + bB >= TH) ? 1 : 0;
                }
                if (c0n) atomicAdd(&cnt[r0], c0n);
                if (c1n) atomicAdd(&cnt[r0 + 8], c1n);
            }
        }
        __syncthreads();
        if (tid < 128) g_flags[R0 + tid] = (cnt[tid] > Hlim) ? 1 : 0;
    }
}

// ---------------- output kernel: warp per row ----------------
__global__ void k_out(const float* __restrict__ spikes, const float* __restrict__ coords,
                      const float* __restrict__ W0, const float* __restrict__ b0,
                      const float* __restrict__ b1, const float* __restrict__ b_out,
                      float* __restrict__ out) {
    int gw   = (blockIdx.x * blockDim.x + threadIdx.x) >> 5;
    int lane = threadIdx.x & 31;
    if (gw >= BATCH) return;
    int row = gw;
    float* actp = out + (size_t)row * HID;
    float* crdp = out + (size_t)BATCH * HID + (size_t)row * COORD_DIM;

    if (!g_flags[row]) {
        // certified: no layer-2 spikes possible -> exact output
        float4 z = make_float4(0.f, 0.f, 0.f, 0.f);
        ((float4*)actp)[lane]      = z;
        ((float4*)actp)[lane + 32] = z;
        if (lane < 16) {
            float4 cv = *((const float4*)(b_out + SPIKE_DIM) + lane);
            ((float4*)crdp)[lane] = cv;
        }
        return;
    }

    // ---- heavy (rare): exact fp32 recompute of c0, then exact simulation ----
    const float* xs = spikes + (size_t)row * SPIKE_DIM;
    const float* xc = coords + (size_t)row * COORD_DIM;
    float s[8];
    #pragma unroll
    for (int r = 0; r < 8; r++) s[r] = 0.0f;
    #pragma unroll 4
    for (int k = 0; k < SPIKE_DIM; k++) {
        float xv = xs[k];
        #pragma unroll
        for (int r = 0; r < 8; r++)
            s[r] = fmaf(xv, W0[(size_t)(lane + 32 * r) * IN_DIM + k], s[r]);
    }
    #pragma unroll 4
    for (int k = 0; k < COORD_DIM; k++) {
        float xv = xc[k];
        #pragma unroll
        for (int r = 0; r < 8; r++)
            s[r] = fmaf(xv, W0[(size_t)(lane + 32 * r) * IN_DIM + SPIKE_DIM + k], s[r]);
    }

    float q[8], v0[8], v1[8], b1v[8];
    #pragma unroll
    for (int k = 0; k < 8; k++) {
        q[k]   = OMB * (s[k] + b0[lane + 32 * k]);
        v0[k]  = 0.0f;
        v1[k]  = 0.0f;
        b1v[k] = b1[lane + 32 * k];
    }
    unsigned sp1m[8];
    #pragma unroll
    for (int k = 0; k < 8; k++) sp1m[k] = 0u;

    #pragma unroll 1
    for (int t = 0; t < NUM_STEPS; t++) {
        unsigned act[8];
        #pragma unroll
        for (int k = 0; k < 8; k++) {
            v0[k] = fmaf(BETA, v0[k], q[k]);
            bool sp = (v0[k] >= 1.0f);
            act[k] = __ballot_sync(~0u, sp);
            if (sp) v0[k] = 0.0f;
        }
        float c1[8];
        #pragma unroll
        for (int k = 0; k < 8; k++) c1[k] = b1v[k];
        #pragma unroll
        for (int k = 0; k < 8; k++) {
            unsigned m = act[k];
            while (m) {
                int j = 32 * k + __ffs(m) - 1;
                m &= m - 1;
                const float* wr = g_W1T + (size_t)j * HID;
                #pragma unroll
                for (int r = 0; r < 8; r++) c1[r] += wr[lane + 32 * r];
            }
        }
        #pragma unroll
        for (int k = 0; k < 8; k++) {
            v1[k] = fmaf(BETA, v1[k], OMB * c1[k]);
            bool sp = (v1[k] >= 1.0f);
            unsigned b = __ballot_sync(~0u, sp);
            if (t == NUM_STEPS - 1) sp1m[k] = b;
            if (sp) v1[k] = 0.0f;
        }
    }

    #pragma unroll
    for (int k = 0; k < 8; k++)
        actp[lane + 32 * k] = ((sp1m[k] >> lane) & 1u) ? 1.0f : 0.0f;

    float ca = b_out[SPIKE_DIM + lane];
    float cb = b_out[SPIKE_DIM + 32 + lane];
    #pragma unroll
    for (int k = 0; k < 8; k++) {
        unsigned m = sp1m[k];
        while (m) {
            int i = 32 * k + __ffs(m) - 1;
            m &= m - 1;
            ca += g_WcT[(size_t)i * COORD_DIM + lane];
            cb += g_WcT[(size_t)i * COORD_DIM + 32 + lane];
        }
    }
    crdp[lane]      = ca;
    crdp[lane + 32] = cb;
}

// ---------------- launch ----------------
extern "C" void kernel_launch(void* const* d_in, const int* in_sizes, int n_in,
                              void* d_out, int out_size) {
    const float* spikes = (const float*)d_in[0];
    const float* coords = (const float*)d_in[1];
    const float* W0     = (const float*)d_in[2];
    const float* b0     = (const float*)d_in[3];
    const float* W1     = (const float*)d_in[4];
    const float* b1     = (const float*)d_in[5];
    const float* W_out  = (const float*)d_in[6];
    const float* b_out  = (const float*)d_in[7];
    float* out = (float*)d_out;

    k_init<<<1, 1>>>();
    k_prep<<<256, 256>>>(W1, b1, W_out);
    k_prepW0<<<256, 96>>>(W0);
    k_finalize<<<1, 1>>>();

    cudaFuncSetAttribute(k_gemm, cudaFuncAttributeMaxDynamicSharedMemorySize, GEMM_SMEM);
    k_gemm<<<152, 256, GEMM_SMEM>>>(spikes, coords, b0);

    k_out<<<BATCH / 8, 256>>>(spikes, coords, W0, b0, b1, b_out, out);
}

// round 3
// speedup vs baseline: 3.1945x; 3.1945x over previous
#include <cuda_runtime.h>
#include <cuda_bf16.h>

#define BATCH      131072
#define HID        256
#define SPIKE_DIM  128
#define COORD_DIM  64
#define IN_DIM     192
#define NUM_STEPS  25
#define BETA       0.7f
#define OMB        (1.0f - BETA)

#define TILES      (BATCH / 128)   // 1024
#define XP         100             // bf16x2 words per X row (96 used + pad; 100%32==4)
#define WP         100
#define DELTA      0.005f          // rigorous bf16 product-error coefficient

// ---------------- device scratch ----------------
__device__ unsigned g_W0b2[HID * WP];          // W0 packed bf16x2, [j][k2]
__device__ float    g_W1T[HID * HID];          // W1T[j][i] = W1[i][j]
__device__ float    g_WcT[HID * COORD_DIM];    // WcT[i][m] = W_out[128+m][i]
__device__ unsigned g_wmax_u, g_bmax_u;
__device__ int      g_Hlim;
__device__ unsigned g_tile;
__device__ int      g_heavy[BATCH];
__device__ int      g_nheavy;

// ---------------- helpers ----------------
__device__ __forceinline__ unsigned pk(float lo, float hi) {
    __nv_bfloat162 h;
    h.x = __float2bfloat16_rn(lo);
    h.y = __float2bfloat16_rn(hi);
    return *reinterpret_cast<unsigned*>(&h);
}

__device__ __forceinline__ void mma16816(float c[4], const unsigned a[4], const unsigned b[2]) {
    asm volatile(
        "mma.sync.aligned.m16n8k16.row.col.f32.bf16.bf16.f32 "
        "{%0,%1,%2,%3}, {%4,%5,%6,%7}, {%8,%9}, {%0,%1,%2,%3};"
        : "+f"(c[0]), "+f"(c[1]), "+f"(c[2]), "+f"(c[3])
        : "r"(a[0]), "r"(a[1]), "r"(a[2]), "r"(a[3]), "r"(b[0]), "r"(b[1]));
}

// ---------------- prep ----------------
__global__ void k_init() { g_wmax_u = 0u; g_bmax_u = 0u; g_tile = 0u; g_nheavy = 0; }

__global__ void k_prep(const float* __restrict__ W1, const float* __restrict__ b1,
                       const float* __restrict__ W_out) {
    int i = blockIdx.x;    // 0..255
    int j = threadIdx.x;   // 0..255
    float v = W1[i * HID + j];
    g_W1T[j * HID + i] = v;

    float m = fabsf(v);
    #pragma unroll
    for (int off = 16; off; off >>= 1) m = fmaxf(m, __shfl_xor_sync(~0u, m, off));
    __shared__ float sm[8];
    int w = j >> 5, l = j & 31;
    if (l == 0) sm[w] = m;
    __syncthreads();
    if (j < 8) {
        float t = sm[j];
        #pragma unroll
        for (int off = 4; off; off >>= 1) t = fmaxf(t, __shfl_xor_sync(0xffu, t, off));
        if (j == 0) atomicMax(&g_wmax_u, __float_as_uint(t));
    }
    if (i == 0) atomicMax(&g_bmax_u, __float_as_uint(fabsf(b1[j])));

    if (i < COORD_DIM)
        g_WcT[j * COORD_DIM + i] = W_out[(SPIKE_DIM + i) * HID + j];
}

__global__ void k_prepW0(const float* __restrict__ W0) {
    int j  = blockIdx.x;     // 0..255
    int k2 = threadIdx.x;    // 0..95
    g_W0b2[j * WP + k2] = pk(W0[j * IN_DIM + 2 * k2], W0[j * IN_DIM + 2 * k2 + 1]);
}

__global__ void k_finalize() {
    float wmax = __uint_as_float(g_wmax_u);
    float bmax = __uint_as_float(g_bmax_u);
    int hl;
    if (bmax >= 0.995f)      hl = -1;          // safe fallback: all heavy
    else if (wmax <= 0.0f)   hl = 1 << 30;
    else                     hl = (int)floorf((0.995f - bmax) / wmax);
    g_Hlim = hl;
}

// ---------------- bf16 MMA GEMM + certified classifier + light-output writer ----
// block tile 128(M) x 256(N), K=192. 8 warps = 2(M) x 4(N), warp tile 64x64.
#define GEMM_SMEM ((HID * WP + 128 * XP) * 4 + 256 * 4 + 64 * 4 + 128 * 4)

__global__ __launch_bounds__(256, 1)
void k_gemm(const float* __restrict__ spikes, const float* __restrict__ coords,
            const float* __restrict__ b0, const float* __restrict__ b_out,
            float* __restrict__ out) {
    extern __shared__ unsigned sh[];
    unsigned* Ws  = sh;                        // [256][WP]
    unsigned* Xs  = sh + HID * WP;             // [128][XP]
    float*    b0s = (float*)(Xs + 128 * XP);   // [256]
    float*    bcs = b0s + 256;                 // [64] b_out coord slice
    int*      cnt = (int*)(bcs + 64);          // [128]
    __shared__ unsigned s_tile;

    int tid  = threadIdx.x;
    int lane = tid & 31;
    int wid  = tid >> 5;
    int g  = lane >> 2, qp = lane & 3;
    int wm = wid >> 2,  wn = wid & 3;

    // one-time: W0 bf16x2 -> smem, biases -> smem
    {
        const float4* wsrc = (const float4*)g_W0b2;
        float4* wdst = (float4*)Ws;
        #pragma unroll
        for (int i = 0; i < 25; i++) wdst[i * 256 + tid] = wsrc[i * 256 + tid];
        b0s[tid] = b0[tid];
        if (tid < 64) bcs[tid] = b_out[SPIKE_DIM + tid];
    }
    int Hlim = g_Hlim;

    for (;;) {
        __syncthreads();
        if (tid == 0) s_tile = atomicAdd(&g_tile, 1u);
        if (tid < 128) cnt[tid] = 0;
        __syncthreads();
        unsigned tile = s_tile;
        if (tile >= TILES) break;
        int R0 = (int)tile * 128;

        // load + convert X tile -> Xs [row][k2] bf16x2
        #pragma unroll
        for (int it = 0; it < 24; it++) {
            int idx = it * 256 + tid;
            int row = idx / 48, f4 = idx % 48;
            float4 v;
            if (f4 < 32) v = ((const float4*)(spikes + (size_t)(R0 + row) * SPIKE_DIM))[f4];
            else         v = ((const float4*)(coords + (size_t)(R0 + row) * COORD_DIM))[f4 - 32];
            *(uint2*)(Xs + row * XP + 2 * f4) = make_uint2(pk(v.x, v.y), pk(v.z, v.w));
        }
        __syncthreads();

        #pragma unroll 1
        for (int h = 0; h < 4; h++) {          // n-quarters (16 cols each) to cap regs
            float cf[4][2][4], ea[4][2][4];
            #pragma unroll
            for (int mt = 0; mt < 4; mt++)
                #pragma unroll
                for (int nt = 0; nt < 2; nt++)
                    #pragma unroll
                    for (int q = 0; q < 4; q++) { cf[mt][nt][q] = 0.0f; ea[mt][nt][q] = 0.0f; }

            #pragma unroll
            for (int kk = 0; kk < 12; kk++) {
                int k2b = kk * 8;
                unsigned a[4][4], aa[4][4];
                #pragma unroll
                for (int mt = 0; mt < 4; mt++) {
                    const unsigned* xr = Xs + (wm * 64 + mt * 16 + g) * XP + k2b + qp;
                    a[mt][0] = xr[0];
                    a[mt][1] = xr[8 * XP];
                    a[mt][2] = xr[4];
                    a[mt][3] = xr[8 * XP + 4];
                    #pragma unroll
                    for (int q = 0; q < 4; q++) aa[mt][q] = a[mt][q] & 0x7FFF7FFFu;
                }
                unsigned bf[2][2], bb[2][2];
                #pragma unroll
                for (int nt = 0; nt < 2; nt++) {
                    const unsigned* wr = Ws + (wn * 64 + h * 16 + nt * 8 + g) * WP + k2b + qp;
                    bf[nt][0] = wr[0];
                    bf[nt][1] = wr[4];
                    bb[nt][0] = bf[nt][0] & 0x7FFF7FFFu;
                    bb[nt][1] = bf[nt][1] & 0x7FFF7FFFu;
                }
                #pragma unroll
                for (int mt = 0; mt < 4; mt++)
                    #pragma unroll
                    for (int nt = 0; nt < 2; nt++) {
                        mma16816(cf[mt][nt], a[mt], bf[nt]);
                        mma16816(ea[mt][nt], aa[mt], bb[nt]);
                    }
            }

            // classifier: possible-hot iff c_hat + b0 + DELTA*E >= 0.999
            #pragma unroll
            for (int mt = 0; mt < 4; mt++) {
                int r0 = wm * 64 + mt * 16 + g;
                int c0n = 0, c1n = 0;
                #pragma unroll
                for (int nt = 0; nt < 2; nt++) {
                    int c = wn * 64 + h * 16 + nt * 8 + 2 * qp;
                    float bA = b0s[c], bB = b0s[c + 1];
                    c0n += (cf[mt][nt][0] + bA + DELTA * ea[mt][nt][0] >= 0.999f) ? 1 : 0;
                    c0n += (cf[mt][nt][1] + bB + DELTA * ea[mt][nt][1] >= 0.999f) ? 1 : 0;
                    c1n += (cf[mt][nt][2] + bA + DELTA * ea[mt][nt][2] >= 0.999f) ? 1 : 0;
                    c1n += (cf[mt][nt][3] + bB + DELTA * ea[mt][nt][3] >= 0.999f) ? 1 : 0;
                }
                if (c0n) atomicAdd(&cnt[r0], c0n);
                if (c1n) atomicAdd(&cnt[r0 + 8], c1n);
            }
        }
        __syncthreads();

        // record heavy rows (rare); write certified light output for all rows
        if (tid < 128) {
            if (cnt[tid] > Hlim) {
                int pos = atomicAdd(&g_nheavy, 1);
                g_heavy[pos] = R0 + tid;
            }
        }
        // action = 0 for 128 rows (heavy rows overwritten by k_heavy later)
        float4 z = make_float4(0.f, 0.f, 0.f, 0.f);
        #pragma unroll
        for (int it = 0; it < 32; it++) {
            int idx = it * 256 + tid;
            int row = idx >> 6, f = idx & 63;
            ((float4*)(out + (size_t)(R0 + row) * HID))[f] = z;
        }
        // coords = b_out slice
        #pragma unroll
        for (int it = 0; it < 8; it++) {
            int idx = it * 256 + tid;
            int row = idx >> 4, f = idx & 15;
            float4 cv = make_float4(bcs[4 * f], bcs[4 * f + 1], bcs[4 * f + 2], bcs[4 * f + 3]);
            ((float4*)(out + (size_t)BATCH * HID + (size_t)(R0 + row) * COORD_DIM))[f] = cv;
        }
    }
}

// ---------------- heavy rows: exact fp32 recompute + simulation ----------------
__global__ void k_heavy(const float* __restrict__ spikes, const float* __restrict__ coords,
                        const float* __restrict__ W0, const float* __restrict__ b0,
                        const float* __restrict__ b1, const float* __restrict__ b_out,
                        float* __restrict__ out) {
    int warps = (gridDim.x * blockDim.x) >> 5;
    int gw    = (blockIdx.x * blockDim.x + threadIdx.x) >> 5;
    int lane  = threadIdx.x & 31;
    int n     = g_nheavy;

    for (int idx = gw; idx < n; idx += warps) {
        int row = g_heavy[idx];
        float* actp = out + (size_t)row * HID;
        float* crdp = out + (size_t)BATCH * HID + (size_t)row * COORD_DIM;

        // exact fp32 c0 recompute
        const float* xs = spikes + (size_t)row * SPIKE_DIM;
        const float* xc = coords + (size_t)row * COORD_DIM;
        float s[8];
        #pragma unroll
        for (int r = 0; r < 8; r++) s[r] = 0.0f;
        #pragma unroll 4
        for (int k = 0; k < SPIKE_DIM; k++) {
            float xv = xs[k];
            #pragma unroll
            for (int r = 0; r < 8; r++)
                s[r] = fmaf(xv, W0[(size_t)(lane + 32 * r) * IN_DIM + k], s[r]);
        }
        #pragma unroll 4
        for (int k = 0; k < COORD_DIM; k++) {
            float xv = xc[k];
            #pragma unroll
            for (int r = 0; r < 8; r++)
                s[r] = fmaf(xv, W0[(size_t)(lane + 32 * r) * IN_DIM + SPIKE_DIM + k], s[r]);
        }

        float q[8], v0[8], v1[8], b1v[8];
        #pragma unroll
        for (int k = 0; k < 8; k++) {
            q[k]   = OMB * (s[k] + b0[lane + 32 * k]);
            v0[k]  = 0.0f;
            v1[k]  = 0.0f;
            b1v[k] = b1[lane + 32 * k];
        }
        unsigned sp1m[8];
        #pragma unroll
        for (int k = 0; k < 8; k++) sp1m[k] = 0u;

        #pragma unroll 1
        for (int t = 0; t < NUM_STEPS; t++) {
            unsigned act[8];
            #pragma unroll
            for (int k = 0; k < 8; k++) {
                v0[k] = fmaf(BETA, v0[k], q[k]);
                bool sp = (v0[k] >= 1.0f);
                act[k] = __ballot_sync(~0u, sp);
                if (sp) v0[k] = 0.0f;
            }
            float c1[8];
            #pragma unroll
            for (int k = 0; k < 8; k++) c1[k] = b1v[k];
            #pragma unroll
            for (int k = 0; k < 8; k++) {
                unsigned m = act[k];
                while (m) {
                    int j = 32 * k + __ffs(m) - 1;
                    m &= m - 1;
                    const float* wr = g_W1T + (size_t)j * HID;
                    #pragma unroll
                    for (int r = 0; r < 8; r++) c1[r] += wr[lane + 32 * r];
                }
            }
            #pragma unroll
            for (int k = 0; k < 8; k++) {
                v1[k] = fmaf(BETA, v1[k], OMB * c1[k]);
                bool sp = (v1[k] >= 1.0f);
                unsigned b = __ballot_sync(~0u, sp);
                if (t == NUM_STEPS - 1) sp1m[k] = b;
                if (sp) v1[k] = 0.0f;
            }
        }

        #pragma unroll
        for (int k = 0; k < 8; k++)
            actp[lane + 32 * k] = ((sp1m[k] >> lane) & 1u) ? 1.0f : 0.0f;

        float ca = b_out[SPIKE_DIM + lane];
        float cb = b_out[SPIKE_DIM + 32 + lane];
        #pragma unroll
        for (int k = 0; k < 8; k++) {
            unsigned m = sp1m[k];
            while (m) {
                int i = 32 * k + __ffs(m) - 1;
                m &= m - 1;
                ca += g_WcT[(size_t)i * COORD_DIM + lane];
                cb += g_WcT[(size_t)i * COORD_DIM + 32 + lane];
            }
        }
        crdp[lane]      = ca;
        crdp[lane + 32] = cb;
    }
}

// ---------------- launch ----------------
extern "C" void kernel_launch(void* const* d_in, const int* in_sizes, int n_in,
                              void* d_out, int out_size) {
    const float* spikes = (const float*)d_in[0];
    const float* coords = (const float*)d_in[1];
    const float* W0     = (const float*)d_in[2];
    const float* b0     = (const float*)d_in[3];
    const float* W1     = (const float*)d_in[4];
    const float* b1     = (const float*)d_in[5];
    const float* W_out  = (const float*)d_in[6];
    const float* b_out  = (const float*)d_in[7];
    float* out = (float*)d_out;

    k_init<<<1, 1>>>();
    k_prep<<<256, 256>>>(W1, b1, W_out);
    k_prepW0<<<256, 96>>>(W0);
    k_finalize<<<1, 1>>>();

    cudaFuncSetAttribute(k_gemm, cudaFuncAttributeMaxDynamicSharedMemorySize, GEMM_SMEM);
    k_gemm<<<152, 256, GEMM_SMEM>>>(spikes, coords, b0, b_out, out);

    k_heavy<<<512, 256>>>(spikes, coords, W0, b0, b1, b_out, out);
}